// round 13
// baseline (speedup 1.0000x reference)
#include <cuda_runtime.h>
#include <cuda_fp16.h>
#include <mma.h>
#include <cstdint>
#include <type_traits>

using namespace nvcuda;

// FHEAttention B=4,S=4096,E=256 — linearized: out = 1e-11 * x @ P @ (x^T x) @ R
// ONE persistent 256-CTA kernel; stages separated by software grid barriers.
// All GEMMs HMMA (wmma fp16, fp32 accum); 1e-11 applied in final epilogue.

#define B_ 4
#define S_ 4096
#define E_ 256
#define GSPLIT 16
#define PAD32 40
#define PADM 136
#define ABUF 5120
#define NCTA 256

// ---------------- scratch ----------------
__device__ __align__(128) __half g_xTh[B_ * E_ * S_];
__device__ __align__(128) float  g_part[B_ * GSPLIT * E_ * E_];   // 16.8 MB
__device__ __align__(128) __half g_Gh[B_ * E_ * E_];
__device__ __align__(128) __half g_R2h[E_ * E_];
__device__ __align__(128) __half g_P2h[E_ * E_];
__device__ __align__(128) __half g_U2h[B_ * E_ * E_];
__device__ __align__(128) __half g_T2h[B_ * E_ * E_];
__device__ unsigned g_bar_arr = 0;
__device__ unsigned g_bar_gen = 0;

// ---------------- cp.async helpers ----------------
__device__ __forceinline__ void cp16(void* smem_dst, const void* gsrc) {
    uint32_t s = (uint32_t)__cvta_generic_to_shared(smem_dst);
    asm volatile("cp.async.cg.shared.global [%0], [%1], 16;" :: "r"(s), "l"(gsrc));
}
#define CP_COMMIT() asm volatile("cp.async.commit_group;")
#define CP_WAIT1()  asm volatile("cp.async.wait_group 1;")
#define CP_WAIT0()  asm volatile("cp.async.wait_group 0;")

// ---------------- software grid barrier (all NCTA CTAs resident) -------------
__device__ __forceinline__ void grid_barrier() {
    __syncthreads();
    if (threadIdx.x == 0) {
        unsigned gen = atomicAdd(&g_bar_gen, 0u);
        __threadfence();
        unsigned t = atomicAdd(&g_bar_arr, 1u);
        if (t == NCTA - 1) {
            atomicExch(&g_bar_arr, 0u);
            __threadfence();
            atomicAdd(&g_bar_gen, 1u);
        } else {
            while (atomicAdd(&g_bar_gen, 0u) == gen) { __nanosleep(64); }
        }
        __threadfence();
    }
    __syncthreads();
}

// ---------------- shared epilogue ----------------
template <int OUTH>
__device__ __forceinline__ void gemm_epilogue(
    wmma::fragment<wmma::accumulator, 16, 16, 16, float> (&acc)[4][2],
    void* Cv, int ldc, float alpha, __half* As, int warp_m, int warp_n)
{
    const int tid = threadIdx.x, wid = tid >> 5;
    if constexpr (OUTH == 0) {
        float* Cb = (float*)Cv;
        #pragma unroll
        for (int i = 0; i < 4; i++)
            #pragma unroll
            for (int j = 0; j < 2; j++) {
                #pragma unroll
                for (int t = 0; t < acc[i][j].num_elements; t++)
                    acc[i][j].x[t] *= alpha;
                wmma::store_matrix_sync(Cb + (long)(warp_m + i * 16) * ldc + warp_n + j * 16,
                                        acc[i][j], ldc, wmma::mem_row_major);
            }
    } else {
        __half* Cb = (__half*)Cv;
        float* patch = ((float*)As) + wid * 256;
        const int lane = tid & 31;
        #pragma unroll
        for (int i = 0; i < 4; i++)
            #pragma unroll
            for (int j = 0; j < 2; j++) {
                wmma::store_matrix_sync(patch, acc[i][j], 16, wmma::mem_row_major);
                __syncwarp();
                #pragma unroll
                for (int e = 0; e < 8; e++) {
                    int el = lane + e * 32;
                    int rr = el >> 4, cc = el & 15;
                    Cb[(long)(warp_m + i * 16 + rr) * ldc + warp_n + j * 16 + cc] =
                        __float2half(patch[el] * alpha);
                }
                __syncwarp();
            }
    }
}

// ---------------- pipelined fp16 GEMM body (cp.async double-buffered) --------
template <int AT, int BT, int OUTH>
__device__ __forceinline__ void gemm_body_pipe(
    const __half* Ap, const __half* Bp, void* Cv,
    int lda, int ldb, int ldc, int Kc, float alpha,
    __half* As, __half* Bs)
{
    const int tid = threadIdx.x, wid = tid >> 5;
    const int warp_m = (wid & 1) * 64;
    const int warp_n = (wid >> 1) * 32;

    wmma::fragment<wmma::accumulator, 16, 16, 16, float> acc[4][2];
    #pragma unroll
    for (int i = 0; i < 4; i++)
        #pragma unroll
        for (int j = 0; j < 2; j++)
            wmma::fill_fragment(acc[i][j], 0.0f);

    using ALay = std::conditional_t<AT == 0, wmma::row_major, wmma::col_major>;
    using BLay = std::conditional_t<BT == 0, wmma::row_major, wmma::col_major>;

    auto stage = [&](int kt, int buf) {
        #pragma unroll
        for (int q = 0; q < 2; q++) {
            int idx = tid + q * 256;
            if constexpr (AT == 0) {
                int r = idx >> 2, c = (idx & 3) * 8;
                cp16(As + buf * ABUF + r * PAD32 + c, Ap + (long)r * lda + kt + c);
            } else {
                int r = idx >> 4, c = (idx & 15) * 8;
                cp16(As + buf * ABUF + r * PADM + c, Ap + (long)(kt + r) * lda + c);
            }
        }
        #pragma unroll
        for (int q = 0; q < 2; q++) {
            int idx = tid + q * 256;
            if constexpr (BT == 0) {
                int r = idx >> 4, c = (idx & 15) * 8;
                cp16(Bs + buf * ABUF + r * PADM + c, Bp + (long)(kt + r) * ldb + c);
            } else {
                int r = idx >> 2, c = (idx & 3) * 8;
                cp16(Bs + buf * ABUF + r * PAD32 + c, Bp + (long)r * ldb + kt + c);
            }
        }
    };

    const int nIter = Kc >> 5;
    int buf = 0;
    stage(0, 0);
    CP_COMMIT();
    for (int it = 0; it < nIter; it++) {
        if (it + 1 < nIter) {
            stage((it + 1) * 32, buf ^ 1);
            CP_COMMIT();
            CP_WAIT1();
        } else {
            CP_WAIT0();
        }
        __syncthreads();
        const __half* Ab = As + buf * ABUF;
        const __half* Bb = Bs + buf * ABUF;
        #pragma unroll
        for (int ks = 0; ks < 32; ks += 16) {
            wmma::fragment<wmma::matrix_a, 16, 16, 16, __half, ALay> af[4];
            wmma::fragment<wmma::matrix_b, 16, 16, 16, __half, BLay> bf[2];
            #pragma unroll
            for (int i = 0; i < 4; i++) {
                if constexpr (AT == 0)
                    wmma::load_matrix_sync(af[i], Ab + (warp_m + i * 16) * PAD32 + ks, PAD32);
                else
                    wmma::load_matrix_sync(af[i], Ab + ks * PADM + warp_m + i * 16, PADM);
            }
            #pragma unroll
            for (int j = 0; j < 2; j++) {
                if constexpr (BT == 0)
                    wmma::load_matrix_sync(bf[j], Bb + ks * PADM + warp_n + j * 16, PADM);
                else
                    wmma::load_matrix_sync(bf[j], Bb + (warp_n + j * 16) * PAD32 + ks, PAD32);
            }
            #pragma unroll
            for (int i = 0; i < 4; i++)
                #pragma unroll
                for (int j = 0; j < 2; j++)
                    wmma::mma_sync(acc[i][j], af[i], bf[j], acc[i][j]);
        }
        buf ^= 1;
        __syncthreads();
    }
    gemm_epilogue<OUTH>(acc, Cv, ldc, alpha, As, warp_m, warp_n);
}

// ---------------- generic body for fp32-staged operands (weights) -----------
template <int AT, int OUTH>
__device__ __forceinline__ void gemm_body_f32(
    const float* Ap, const float* Bp, void* Cv,
    int lda, int ldb, int ldc, int Kc, float alpha,
    __half* As, __half* Bs)
{
    const int tid = threadIdx.x, wid = tid >> 5;
    const int warp_m = (wid & 1) * 64;
    const int warp_n = (wid >> 1) * 32;

    wmma::fragment<wmma::accumulator, 16, 16, 16, float> acc[4][2];
    #pragma unroll
    for (int i = 0; i < 4; i++)
        #pragma unroll
        for (int j = 0; j < 2; j++)
            wmma::fill_fragment(acc[i][j], 0.0f);

    using ALay = std::conditional_t<AT == 0, wmma::row_major, wmma::col_major>;

    for (int kt = 0; kt < Kc; kt += 32) {
        if constexpr (AT == 0) {
            const float* Aq = Ap + kt;
            #pragma unroll
            for (int q = 0; q < 4; q++) {
                int idx = tid + q * 256;
                int r = idx >> 3, c = (idx & 7) * 4;
                float4 v = *(const float4*)(Aq + (long)r * lda + c);
                __half2 h0 = __floats2half2_rn(v.x, v.y);
                __half2 h1 = __floats2half2_rn(v.z, v.w);
                uint2 o; o.x = *(uint32_t*)&h0; o.y = *(uint32_t*)&h1;
                *(uint2*)(As + r * PAD32 + c) = o;
            }
        } else {
            const float* Aq = Ap + (long)kt * lda;
            #pragma unroll
            for (int q = 0; q < 4; q++) {
                int idx = tid + q * 256;
                int r = idx >> 5, c = (idx & 31) * 4;
                float4 v = *(const float4*)(Aq + (long)r * lda + c);
                __half2 h0 = __floats2half2_rn(v.x, v.y);
                __half2 h1 = __floats2half2_rn(v.z, v.w);
                uint2 o; o.x = *(uint32_t*)&h0; o.y = *(uint32_t*)&h1;
                *(uint2*)(As + r * PADM + c) = o;
            }
        }
        {
            const float* Bq = Bp + (long)kt * ldb;
            #pragma unroll
            for (int q = 0; q < 4; q++) {
                int idx = tid + q * 256;
                int r = idx >> 5, c = (idx & 31) * 4;
                float4 v = *(const float4*)(Bq + (long)r * ldb + c);
                __half2 h0 = __floats2half2_rn(v.x, v.y);
                __half2 h1 = __floats2half2_rn(v.z, v.w);
                uint2 o; o.x = *(uint32_t*)&h0; o.y = *(uint32_t*)&h1;
                *(uint2*)(Bs + r * PADM + c) = o;
            }
        }
        __syncthreads();
        #pragma unroll
        for (int ks = 0; ks < 32; ks += 16) {
            wmma::fragment<wmma::matrix_a, 16, 16, 16, __half, ALay> af[4];
            wmma::fragment<wmma::matrix_b, 16, 16, 16, __half, wmma::row_major> bf[2];
            #pragma unroll
            for (int i = 0; i < 4; i++) {
                if constexpr (AT == 0)
                    wmma::load_matrix_sync(af[i], As + (warp_m + i * 16) * PAD32 + ks, PAD32);
                else
                    wmma::load_matrix_sync(af[i], As + ks * PADM + warp_m + i * 16, PADM);
            }
            #pragma unroll
            for (int j = 0; j < 2; j++)
                wmma::load_matrix_sync(bf[j], Bs + ks * PADM + warp_n + j * 16, PADM);
            #pragma unroll
            for (int i = 0; i < 4; i++)
                #pragma unroll
                for (int j = 0; j < 2; j++)
                    wmma::mma_sync(acc[i][j], af[i], bf[j], acc[i][j]);
        }
        __syncthreads();
    }
    gemm_epilogue<OUTH>(acc, Cv, ldc, alpha, As, warp_m, warp_n);
}

// ---------------- THE persistent kernel ----------------
__global__ __launch_bounds__(256, 2) void fused_all(
    const float* __restrict__ x,
    const float* __restrict__ Wq, const float* __restrict__ Wk,
    const float* __restrict__ Wv, const float* __restrict__ Wo,
    float* __restrict__ out,
    __half* __restrict__ xTh, float* __restrict__ part,
    __half* __restrict__ Gh, __half* __restrict__ R2, __half* __restrict__ P2,
    __half* __restrict__ U2, __half* __restrict__ T2)
{
    __shared__ __align__(32) __half As[2 * ABUF];
    __shared__ __align__(32) __half Bs[2 * ABUF];
    const int cta = blockIdx.x;
    const int tid = threadIdx.x;
    const long EE = (long)E_ * E_;
    const long ES = (long)E_ * S_;
    const long SE = (long)S_ * E_;

    // ==== stage 0: CTAs 0-247 convert x -> xT fp16; CTAs 248-255 R2/P2 ====
    if (cta < 248) {
        __half (*sh)[33] = (__half(*)[33])As;   // 32x33 halves, stage-local
        const int j = tid & 31, i0 = (tid >> 5) * 4;
        for (int job = cta; job < 4096; job += 248) {
            const int e0 = (job & 7) * 32;
            const int s0 = ((job >> 3) & 127) * 32;
            const int b = job >> 10;
            const long xb = (long)b * SE;
            #pragma unroll
            for (int ii = 0; ii < 4; ii++) {
                int i = i0 + ii;
                sh[i][j] = __float2half(x[xb + (long)(s0 + i) * E_ + e0 + j]);
            }
            __syncthreads();
            const long xtb = (long)b * ES;
            #pragma unroll
            for (int ii = 0; ii < 4; ii++) {
                int i = i0 + ii;
                xTh[xtb + (long)(e0 + i) * S_ + s0 + j] = sh[j][i];
            }
            __syncthreads();
        }
    } else {
        const int c = cta - 248;          // 0..7
        const int bx = c & 3;
        const int m0 = (bx >> 1) * 128, n0 = (bx & 1) * 128;
        if (c < 4)
            gemm_body_f32<0, 1>(Wo + (long)m0 * E_, Wv + n0,
                                (void*)(R2 + (long)m0 * E_ + n0),
                                E_, E_, E_, E_, 1.0f, As, Bs);
        else
            gemm_body_f32<1, 1>(Wk + m0, Wq + n0,
                                (void*)(P2 + (long)m0 * E_ + n0),
                                E_, E_, E_, E_, 1.0f, As, Bs);
    }
    grid_barrier();

    // ==== stage 1: Gram partials, 256 jobs (4 mn x 16 splits x 4 batches) ====
    {
        const int bz = cta >> 6;
        const int r = cta & 63;
        const int by = r >> 2;            // split 0..15
        const int bx = r & 3;
        const int m0 = (bx >> 1) * 128, n0 = (bx & 1) * 128;
        const int Kc = S_ / GSPLIT;       // 256
        gemm_body_pipe<0, 1, 0>(
            xTh + (long)bz * ES + (long)m0 * S_ + (long)by * Kc,
            xTh + (long)bz * ES + (long)n0 * S_ + (long)by * Kc,
            (void*)(part + ((long)(bz * GSPLIT + by)) * EE + (long)m0 * E_ + n0),
            S_, S_, E_, Kc, 1.0f, As, Bs);
    }
    grid_barrier();

    // ==== stage 2: fixed-order reduce -> G fp16 (1 float4 per thread) ====
    {
        const int i4 = cta * 256 + tid;           // 0 .. 65535 = B_*EE/4
        const int b = i4 >> 14;
        const int r = i4 & 16383;
        const float4* p = (const float4*)part + (long)b * GSPLIT * 16384 + r;
        float4 s = make_float4(0.f, 0.f, 0.f, 0.f);
        #pragma unroll
        for (int q = 0; q < GSPLIT; q++) {
            float4 v = p[(long)q * 16384];
            s.x += v.x; s.y += v.y; s.z += v.z; s.w += v.w;
        }
        __half2 h0 = __floats2half2_rn(s.x, s.y);
        __half2 h1 = __floats2half2_rn(s.z, s.w);
        uint2 o;
        o.x = *(uint32_t*)&h0;
        o.y = *(uint32_t*)&h1;
        *((uint2*)Gh + i4) = o;
    }
    grid_barrier();

    // ==== stage 3: U2_b = R2 · G_b (16 CTAs) ====
    if (cta < 16) {
        const int bz = cta >> 2, bx = cta & 3;
        const int m0 = (bx >> 1) * 128, n0 = (bx & 1) * 128;
        gemm_body_pipe<0, 0, 1>(R2 + (long)m0 * E_, Gh + (long)bz * EE + n0,
                                (void*)(U2 + (long)bz * EE + (long)m0 * E_ + n0),
                                E_, E_, E_, E_, 1.0f, As, Bs);
    }
    grid_barrier();

    // ==== stage 4: T2_b = U2_b · P2 (16 CTAs) ====
    if (cta < 16) {
        const int bz = cta >> 2, bx = cta & 3;
        const int m0 = (bx >> 1) * 128, n0 = (bx & 1) * 128;
        gemm_body_pipe<0, 0, 1>(U2 + (long)bz * EE + (long)m0 * E_, P2 + n0,
                                (void*)(T2 + (long)bz * EE + (long)m0 * E_ + n0),
                                E_, E_, E_, E_, 1.0f, As, Bs);
    }
    grid_barrier();

    // ==== stage 5: final out = 1e-11 * x @ T2^T, 256 jobs ====
    {
        const int bz = cta >> 6;
        const int r = cta & 63;
        const int m0 = (r >> 1) * 128;
        const int n0 = (r & 1) * 128;
        gemm_body_pipe<1, 1, 0>(
            xTh + (long)bz * ES + m0,
            T2 + (long)bz * EE + (long)n0 * E_,
            (void*)(out + (long)bz * SE + (long)m0 * E_ + n0),
            S_, E_, E_, E_, 1e-11f, As, Bs);
    }
}

// ---------------- launch ----------------
extern "C" void kernel_launch(void* const* d_in, const int* in_sizes, int n_in,
                              void* d_out, int out_size)
{
    const float* x  = (const float*)d_in[0];
    const float* Wq = (const float*)d_in[1];
    const float* Wk = (const float*)d_in[2];
    const float* Wv = (const float*)d_in[3];
    const float* Wo = (const float*)d_in[4];
    float* out = (float*)d_out;

    __half *pxTh, *pGh, *pR2h, *pP2h, *pU2h, *pT2h;
    float *pPart;
    cudaGetSymbolAddress((void**)&pxTh, g_xTh);
    cudaGetSymbolAddress((void**)&pPart, g_part);
    cudaGetSymbolAddress((void**)&pGh, g_Gh);
    cudaGetSymbolAddress((void**)&pR2h, g_R2h);
    cudaGetSymbolAddress((void**)&pP2h, g_P2h);
    cudaGetSymbolAddress((void**)&pU2h, g_U2h);
    cudaGetSymbolAddress((void**)&pT2h, g_T2h);

    fused_all<<<NCTA, 256>>>(x, Wq, Wk, Wv, Wo, out,
                             pxTh, pPart, pGh, pR2h, pP2h, pU2h, pT2h);
}

// round 14
// speedup vs baseline: 1.0690x; 1.0690x over previous
#include <cuda_runtime.h>
#include <cuda_fp16.h>
#include <mma.h>
#include <cstdint>
#include <type_traits>

using namespace nvcuda;

// FHEAttention B=4,S=4096,E=256 — linearized: out = 1e-11 * x @ P @ (x^T x) @ R
// All GEMMs HMMA (wmma fp16, fp32 accum); 1e-11 applied in final epilogue.
// No transpose: Gram reads x fp16 as col-major (AT=1); final reads it row-major.
// Heavy GEMMs: 3-stage cp.async ring, one __syncthreads per k-iter.

#define B_ 4
#define S_ 4096
#define E_ 256
#define GSPLIT 16
#define PAD32 40
#define PADM 136
#define ABUF 5120
#define NMID 64

// ---------------- scratch ----------------
__device__ __align__(128) __half g_xh[B_ * S_ * E_];              // x fp16 row-major
__device__ __align__(128) float  g_part[B_ * GSPLIT * E_ * E_];   // 16.8 MB
__device__ __align__(128) __half g_Gh[B_ * E_ * E_];
__device__ __align__(128) __half g_R2h[E_ * E_];
__device__ __align__(128) __half g_P2h[E_ * E_];
__device__ __align__(128) __half g_U2h[B_ * E_ * E_];
__device__ __align__(128) __half g_T2h[B_ * E_ * E_];
__device__ unsigned g_bar_arr = 0;
__device__ unsigned g_bar_gen = 0;

// ---------------- cp.async helpers ----------------
__device__ __forceinline__ void cp16(void* smem_dst, const void* gsrc) {
    uint32_t s = (uint32_t)__cvta_generic_to_shared(smem_dst);
    asm volatile("cp.async.cg.shared.global [%0], [%1], 16;" :: "r"(s), "l"(gsrc));
}
#define CP_COMMIT() asm volatile("cp.async.commit_group;")
template <int N> __device__ __forceinline__ void cp_wait() {
    asm volatile("cp.async.wait_group %0;" :: "n"(N));
}

// ---------------- software grid barrier ----------------
__device__ __forceinline__ void grid_barrier(unsigned nCTA) {
    __syncthreads();
    if (threadIdx.x == 0) {
        unsigned gen = atomicAdd(&g_bar_gen, 0u);
        __threadfence();
        unsigned t = atomicAdd(&g_bar_arr, 1u);
        if (t == nCTA - 1) {
            atomicExch(&g_bar_arr, 0u);
            __threadfence();
            atomicAdd(&g_bar_gen, 1u);
        } else {
            while (atomicAdd(&g_bar_gen, 0u) == gen) { __nanosleep(64); }
        }
        __threadfence();
    }
    __syncthreads();
}

// ---------------- shared epilogue ----------------
template <int OUTH>
__device__ __forceinline__ void gemm_epilogue(
    wmma::fragment<wmma::accumulator, 16, 16, 16, float> (&acc)[4][2],
    void* Cv, int ldc, float alpha, __half* As, int warp_m, int warp_n)
{
    const int tid = threadIdx.x, wid = tid >> 5;
    if constexpr (OUTH == 0) {
        float* Cb = (float*)Cv;
        #pragma unroll
        for (int i = 0; i < 4; i++)
            #pragma unroll
            for (int j = 0; j < 2; j++) {
                #pragma unroll
                for (int t = 0; t < acc[i][j].num_elements; t++)
                    acc[i][j].x[t] *= alpha;
                wmma::store_matrix_sync(Cb + (long)(warp_m + i * 16) * ldc + warp_n + j * 16,
                                        acc[i][j], ldc, wmma::mem_row_major);
            }
    } else {
        __half* Cb = (__half*)Cv;
        float* patch = ((float*)As) + wid * 256;
        const int lane = tid & 31;
        #pragma unroll
        for (int i = 0; i < 4; i++)
            #pragma unroll
            for (int j = 0; j < 2; j++) {
                wmma::store_matrix_sync(patch, acc[i][j], 16, wmma::mem_row_major);
                __syncwarp();
                #pragma unroll
                for (int e = 0; e < 8; e++) {
                    int el = lane + e * 32;
                    int rr = el >> 4, cc = el & 15;
                    Cb[(long)(warp_m + i * 16 + rr) * ldc + warp_n + j * 16 + cc] =
                        __float2half(patch[el] * alpha);
                }
                __syncwarp();
            }
    }
}

// ---------------- pipelined fp16 GEMM body (NSTAGE-ring cp.async) ------------
// C[m,n] = alpha * sum_k A(m,k)*B(k,n); 128x128 tile; pointers pre-offset.
// AT=0: A [m][k]; AT=1: A [k][m]. BT=0: B [k][n]; BT=1: B [n][k].
template <int AT, int BT, int OUTH, int NSTAGE>
__device__ __forceinline__ void gemm_body_pipe(
    const __half* Ap, const __half* Bp, void* Cv,
    int lda, int ldb, int ldc, int Kc, float alpha,
    __half* As, __half* Bs)
{
    const int tid = threadIdx.x, wid = tid >> 5;
    const int warp_m = (wid & 1) * 64;
    const int warp_n = (wid >> 1) * 32;

    wmma::fragment<wmma::accumulator, 16, 16, 16, float> acc[4][2];
    #pragma unroll
    for (int i = 0; i < 4; i++)
        #pragma unroll
        for (int j = 0; j < 2; j++)
            wmma::fill_fragment(acc[i][j], 0.0f);

    using ALay = std::conditional_t<AT == 0, wmma::row_major, wmma::col_major>;
    using BLay = std::conditional_t<BT == 0, wmma::row_major, wmma::col_major>;

    auto stage = [&](int itile) {
        const int buf = itile % NSTAGE;
        const int kt = itile * 32;
        #pragma unroll
        for (int q = 0; q < 2; q++) {
            int idx = tid + q * 256;
            if constexpr (AT == 0) {
                int r = idx >> 2, c = (idx & 3) * 8;
                cp16(As + buf * ABUF + r * PAD32 + c, Ap + (long)r * lda + kt + c);
            } else {
                int r = idx >> 4, c = (idx & 15) * 8;
                cp16(As + buf * ABUF + r * PADM + c, Ap + (long)(kt + r) * lda + c);
            }
        }
        #pragma unroll
        for (int q = 0; q < 2; q++) {
            int idx = tid + q * 256;
            if constexpr (BT == 0) {
                int r = idx >> 4, c = (idx & 15) * 8;
                cp16(Bs + buf * ABUF + r * PADM + c, Bp + (long)(kt + r) * ldb + c);
            } else {
                int r = idx >> 2, c = (idx & 3) * 8;
                cp16(Bs + buf * ABUF + r * PAD32 + c, Bp + (long)r * ldb + kt + c);
            }
        }
    };

    const int nIter = Kc >> 5;
    #pragma unroll
    for (int s = 0; s < NSTAGE - 1; s++)
        if (s < nIter) { stage(s); CP_COMMIT(); }

    for (int it = 0; it < nIter; it++) {
        // Buffer it%NSTAGE was committed NSTAGE-1 groups ago -> wait leaves
        // up to NSTAGE-2 newer groups in flight.
        if (it == nIter - 1) cp_wait<0>();
        else                 cp_wait<NSTAGE - 2>();
        __syncthreads();   // all warps done with mma(it-1); buffer it visible
        if (it + NSTAGE - 1 < nIter) { stage(it + NSTAGE - 1); CP_COMMIT(); }

        const __half* Ab = As + (it % NSTAGE) * ABUF;
        const __half* Bb = Bs + (it % NSTAGE) * ABUF;
        #pragma unroll
        for (int ks = 0; ks < 32; ks += 16) {
            wmma::fragment<wmma::matrix_a, 16, 16, 16, __half, ALay> af[4];
            wmma::fragment<wmma::matrix_b, 16, 16, 16, __half, BLay> bf[2];
            #pragma unroll
            for (int i = 0; i < 4; i++) {
                if constexpr (AT == 0)
                    wmma::load_matrix_sync(af[i], Ab + (warp_m + i * 16) * PAD32 + ks, PAD32);
                else
                    wmma::load_matrix_sync(af[i], Ab + ks * PADM + warp_m + i * 16, PADM);
            }
            #pragma unroll
            for (int j = 0; j < 2; j++) {
                if constexpr (BT == 0)
                    wmma::load_matrix_sync(bf[j], Bb + ks * PADM + warp_n + j * 16, PADM);
                else
                    wmma::load_matrix_sync(bf[j], Bb + (warp_n + j * 16) * PAD32 + ks, PAD32);
            }
            #pragma unroll
            for (int i = 0; i < 4; i++)
                #pragma unroll
                for (int j = 0; j < 2; j++)
                    wmma::mma_sync(acc[i][j], af[i], bf[j], acc[i][j]);
        }
    }
    if constexpr (OUTH == 1) __syncthreads();   // before reusing As as patch
    gemm_epilogue<OUTH>(acc, Cv, ldc, alpha, As, warp_m, warp_n);
}

// ---------------- generic body for fp32-staged operands (weights) -----------
template <int AT, int OUTH>
__device__ __forceinline__ void gemm_body_f32(
    const float* Ap, const float* Bp, void* Cv,
    int lda, int ldb, int ldc, int Kc, float alpha,
    __half* As, __half* Bs)
{
    const int tid = threadIdx.x, wid = tid >> 5;
    const int warp_m = (wid & 1) * 64;
    const int warp_n = (wid >> 1) * 32;

    wmma::fragment<wmma::accumulator, 16, 16, 16, float> acc[4][2];
    #pragma unroll
    for (int i = 0; i < 4; i++)
        #pragma unroll
        for (int j = 0; j < 2; j++)
            wmma::fill_fragment(acc[i][j], 0.0f);

    using ALay = std::conditional_t<AT == 0, wmma::row_major, wmma::col_major>;

    for (int kt = 0; kt < Kc; kt += 32) {
        if constexpr (AT == 0) {
            const float* Aq = Ap + kt;
            #pragma unroll
            for (int q = 0; q < 4; q++) {
                int idx = tid + q * 256;
                int r = idx >> 3, c = (idx & 7) * 4;
                float4 v = *(const float4*)(Aq + (long)r * lda + c);
                __half2 h0 = __floats2half2_rn(v.x, v.y);
                __half2 h1 = __floats2half2_rn(v.z, v.w);
                uint2 o; o.x = *(uint32_t*)&h0; o.y = *(uint32_t*)&h1;
                *(uint2*)(As + r * PAD32 + c) = o;
            }
        } else {
            const float* Aq = Ap + (long)kt * lda;
            #pragma unroll
            for (int q = 0; q < 4; q++) {
                int idx = tid + q * 256;
                int r = idx >> 5, c = (idx & 31) * 4;
                float4 v = *(const float4*)(Aq + (long)r * lda + c);
                __half2 h0 = __floats2half2_rn(v.x, v.y);
                __half2 h1 = __floats2half2_rn(v.z, v.w);
                uint2 o; o.x = *(uint32_t*)&h0; o.y = *(uint32_t*)&h1;
                *(uint2*)(As + r * PADM + c) = o;
            }
        }
        {
            const float* Bq = Bp + (long)kt * ldb;
            #pragma unroll
            for (int q = 0; q < 4; q++) {
                int idx = tid + q * 256;
                int r = idx >> 5, c = (idx & 31) * 4;
                float4 v = *(const float4*)(Bq + (long)r * ldb + c);
                __half2 h0 = __floats2half2_rn(v.x, v.y);
                __half2 h1 = __floats2half2_rn(v.z, v.w);
                uint2 o; o.x = *(uint32_t*)&h0; o.y = *(uint32_t*)&h1;
                *(uint2*)(Bs + r * PADM + c) = o;
            }
        }
        __syncthreads();
        #pragma unroll
        for (int ks = 0; ks < 32; ks += 16) {
            wmma::fragment<wmma::matrix_a, 16, 16, 16, __half, ALay> af[4];
            wmma::fragment<wmma::matrix_b, 16, 16, 16, __half, wmma::row_major> bf[2];
            #pragma unroll
            for (int i = 0; i < 4; i++) {
                if constexpr (AT == 0)
                    wmma::load_matrix_sync(af[i], As + (warp_m + i * 16) * PAD32 + ks, PAD32);
                else
                    wmma::load_matrix_sync(af[i], As + ks * PADM + warp_m + i * 16, PADM);
            }
            #pragma unroll
            for (int j = 0; j < 2; j++)
                wmma::load_matrix_sync(bf[j], Bs + ks * PADM + warp_n + j * 16, PADM);
            #pragma unroll
            for (int i = 0; i < 4; i++)
                #pragma unroll
                for (int j = 0; j < 2; j++)
                    wmma::mma_sync(acc[i][j], af[i], bf[j], acc[i][j]);
        }
        __syncthreads();
    }
    gemm_epilogue<OUTH>(acc, Cv, ldc, alpha, As, warp_m, warp_n);
}

// ---------------- pipelined kernel wrapper (3-stage, dynamic smem) ----------
template <int AT, int BT, int OUTH>
__global__ __launch_bounds__(256, 2) void gemm_k(
    const __half* __restrict__ A, const __half* __restrict__ B, void* Cv,
    int lda, int ldb, int ldc, int Kc,
    long sAz, long sBz, long sCz, long sCy, float alpha)
{
    extern __shared__ __half smem[];
    __half* As = smem;
    __half* Bs = smem + 3 * ABUF;
    const int bx = blockIdx.x, by = blockIdx.y, bz = blockIdx.z;
    const int m0 = (bx >> 1) * 128, n0 = (bx & 1) * 128;

    const __half* Ab;
    if constexpr (AT == 0) Ab = A + (long)bz * sAz + (long)m0 * lda + (long)by * Kc;
    else                   Ab = A + (long)bz * sAz + (long)by * Kc * lda + m0;
    const __half* Bb;
    if constexpr (BT == 0) Bb = B + (long)bz * sBz + (long)by * Kc * ldb + n0;
    else                   Bb = B + (long)bz * sBz + (long)n0 * ldb + (long)by * Kc;
    const long coff = (long)bz * sCz + (long)by * sCy + (long)m0 * ldc + n0;
    void* Cb;
    if constexpr (OUTH == 0) Cb = (void*)((float*)Cv + coff);
    else                     Cb = (void*)((__half*)Cv + coff);

    gemm_body_pipe<AT, BT, OUTH, 3>(Ab, Bb, Cb, lda, ldb, ldc, Kc, alpha, As, Bs);
}

// ---------------- persistent mid kernel: reduce + R2/P2 -> U2 -> T2 ----------
__global__ __launch_bounds__(256, 2) void mid_chain(
    const float* __restrict__ Wo, const float* __restrict__ Wv,
    const float* __restrict__ Wk, const float* __restrict__ Wq,
    const float* __restrict__ part,
    __half* __restrict__ Gh, __half* __restrict__ R2, __half* __restrict__ P2,
    __half* __restrict__ U2, __half* __restrict__ T2)
{
    __shared__ __align__(32) __half As[2 * ABUF];
    __shared__ __align__(32) __half Bs[2 * ABUF];
    const int cta = blockIdx.x;
    const long EE = (long)E_ * E_;

    // ---- stage 0: CTAs 0-7 weight products; CTAs 8-63 split-K reduce ----
    if (cta < 8) {
        const int bx = cta & 3;
        const int m0 = (bx >> 1) * 128, n0 = (bx & 1) * 128;
        if (cta < 4)
            gemm_body_f32<0, 1>(Wo + (long)m0 * E_, Wv + n0,
                                (void*)(R2 + (long)m0 * E_ + n0),
                                E_, E_, E_, E_, 1.0f, As, Bs);
        else
            gemm_body_f32<1, 1>(Wk + m0, Wq + n0,
                                (void*)(P2 + (long)m0 * E_ + n0),
                                E_, E_, E_, E_, 1.0f, As, Bs);
    } else {
        for (int i4 = (cta - 8) * 256 + threadIdx.x; i4 < B_ * E_ * E_ / 4;
             i4 += (NMID - 8) * 256) {
            const int b = i4 >> 14;
            const int r = i4 & 16383;
            const float4* p = (const float4*)part + (long)b * GSPLIT * 16384 + r;
            float4 s = make_float4(0.f, 0.f, 0.f, 0.f);
            #pragma unroll
            for (int q = 0; q < GSPLIT; q++) {
                float4 v = p[(long)q * 16384];
                s.x += v.x; s.y += v.y; s.z += v.z; s.w += v.w;
            }
            __half2 h0 = __floats2half2_rn(s.x, s.y);
            __half2 h1 = __floats2half2_rn(s.z, s.w);
            uint2 o;
            o.x = *(uint32_t*)&h0;
            o.y = *(uint32_t*)&h1;
            *((uint2*)Gh + i4) = o;
        }
    }
    grid_barrier(NMID);

    // ---- stage 1: CTAs 0-15: U2_b = R2 · G_b ----
    if (cta < 16) {
        const int bz = cta >> 2, bx = cta & 3;
        const int m0 = (bx >> 1) * 128, n0 = (bx & 1) * 128;
        gemm_body_pipe<0, 0, 1, 2>(R2 + (long)m0 * E_, Gh + (long)bz * EE + n0,
                                   (void*)(U2 + (long)bz * EE + (long)m0 * E_ + n0),
                                   E_, E_, E_, E_, 1.0f, As, Bs);
    }
    grid_barrier(NMID);

    // ---- stage 2: CTAs 0-15: T2_b = U2_b · P2 ----
    if (cta < 16) {
        const int bz = cta >> 2, bx = cta & 3;
        const int m0 = (bx >> 1) * 128, n0 = (bx & 1) * 128;
        gemm_body_pipe<0, 0, 1, 2>(U2 + (long)bz * EE + (long)m0 * E_, P2 + n0,
                                   (void*)(T2 + (long)bz * EE + (long)m0 * E_ + n0),
                                   E_, E_, E_, E_, 1.0f, As, Bs);
    }
}

// ---------------- flat convert x -> fp16 (no transpose) ----------
__global__ __launch_bounds__(256) void convert_x(
    const float4* __restrict__ x4, uint2* __restrict__ xh4)
{
    const int i = blockIdx.x * 256 + threadIdx.x;    // over B_*S_*E_/4
    float4 v = x4[i];
    __half2 h0 = __floats2half2_rn(v.x, v.y);
    __half2 h1 = __floats2half2_rn(v.z, v.w);
    uint2 o;
    o.x = *(uint32_t*)&h0;
    o.y = *(uint32_t*)&h1;
    xh4[i] = o;
}

// ---------------- launch ----------------
extern "C" void kernel_launch(void* const* d_in, const int* in_sizes, int n_in,
                              void* d_out, int out_size)
{
    const float* x  = (const float*)d_in[0];
    const float* Wq = (const float*)d_in[1];
    const float* Wk = (const float*)d_in[2];
    const float* Wv = (const float*)d_in[3];
    const float* Wo = (const float*)d_in[4];
    float* out = (float*)d_out;

    __half *pxh, *pGh, *pR2h, *pP2h, *pU2h, *pT2h;
    float *pPart;
    cudaGetSymbolAddress((void**)&pxh, g_xh);
    cudaGetSymbolAddress((void**)&pPart, g_part);
    cudaGetSymbolAddress((void**)&pGh, g_Gh);
    cudaGetSymbolAddress((void**)&pR2h, g_R2h);
    cudaGetSymbolAddress((void**)&pP2h, g_P2h);
    cudaGetSymbolAddress((void**)&pU2h, g_U2h);
    cudaGetSymbolAddress((void**)&pT2h, g_T2h);

    const long EE = (long)E_ * E_;
    const long SE = (long)S_ * E_;
    const int SMEM3 = 3 * ABUF * 2 * 2;   // 61440 B

    cudaFuncSetAttribute(gemm_k<1, 0, 0>,
                         cudaFuncAttributeMaxDynamicSharedMemorySize, SMEM3);
    cudaFuncSetAttribute(gemm_k<0, 1, 0>,
                         cudaFuncAttributeMaxDynamicSharedMemorySize, SMEM3);

    // 1) flat convert x -> fp16 row-major
    convert_x<<<B_ * S_ * E_ / 4 / 256, 256>>>((const float4*)x, (uint2*)pxh);

    // 2) Gram partials: G_part[e,f] = sum_{s-chunk} x[s,e]x[s,f]
    //    A = x fp16 as [k=s][m=e] (AT=1), B same as [k][n] (BT=0), Kc=256
    gemm_k<1, 0, 0><<<dim3(4, GSPLIT, B_), 256, SMEM3>>>(
        pxh, pxh, pPart, E_, E_, E_, S_ / GSPLIT,
        SE, SE, (long)GSPLIT * EE, EE, 1.0f);

    // 3) persistent middle: reduce + R2/P2 (concurrent) -> U2 -> T2
    mid_chain<<<NMID, 256>>>(Wo, Wv, Wk, Wq, pPart, pGh, pR2h, pP2h, pU2h, pT2h);

    // 4) final: out[s,g] = 1e-11 * sum_f x[s,f] * T2[g,f]  (AT=0, BT=1)
    gemm_k<0, 1, 0><<<dim3((S_ / 128) * 2, 1, B_), 256, SMEM3>>>(
        pxh, pT2h, out, E_, E_, E_, E_,
        SE, EE, SE, 0, 1e-11f);
}

// round 17
// speedup vs baseline: 1.0794x; 1.0098x over previous
#include <cuda_runtime.h>
#include <cuda_fp16.h>
#include <mma.h>
#include <cstdint>
#include <type_traits>

using namespace nvcuda;

// FHEAttention B=4,S=4096,E=256 — linearized: out = 1e-11 * x @ P @ (x^T x) @ R
// Big GEMMs: 128x256 CTA tiles (64x64 warp tiles), 2-stage cp.async double
// buffer (61440 B dynamic smem — proven config), single 128-CTA wave.
// Mid chain: persistent 64-CTA kernel w/ grid barriers.

#define B_ 4
#define S_ 4096
#define E_ 256
#define GSPLIT 16
#define PAD32 40
#define PADM 136
#define PADN 264
#define ABUF 5120
#define ASZ 5120           // per-stage A halves (max of 128*40, 32*136)
#define BSZ 10240          // per-stage B halves (max of 32*264, 256*40)
#define NST 2
#define NMID 64

// ---------------- scratch ----------------
__device__ __align__(128) __half g_xh[B_ * S_ * E_];              // x fp16 row-major
__device__ __align__(128) float  g_part[B_ * GSPLIT * E_ * E_];   // 16.8 MB
__device__ __align__(128) __half g_Gh[B_ * E_ * E_];
__device__ __align__(128) __half g_R2h[E_ * E_];
__device__ __align__(128) __half g_P2h[E_ * E_];
__device__ __align__(128) __half g_U2h[B_ * E_ * E_];
__device__ __align__(128) __half g_T2h[B_ * E_ * E_];
__device__ unsigned g_bar_arr = 0;
__device__ unsigned g_bar_gen = 0;

// ---------------- cp.async helpers ----------------
__device__ __forceinline__ void cp16(void* smem_dst, const void* gsrc) {
    uint32_t s = (uint32_t)__cvta_generic_to_shared(smem_dst);
    asm volatile("cp.async.cg.shared.global [%0], [%1], 16;" :: "r"(s), "l"(gsrc));
}
#define CP_COMMIT() asm volatile("cp.async.commit_group;")
template <int N> __device__ __forceinline__ void cp_wait() {
    asm volatile("cp.async.wait_group %0;" :: "n"(N));
}

// ---------------- software grid barrier ----------------
__device__ __forceinline__ void grid_barrier(unsigned nCTA) {
    __syncthreads();
    if (threadIdx.x == 0) {
        unsigned gen = atomicAdd(&g_bar_gen, 0u);
        __threadfence();
        unsigned t = atomicAdd(&g_bar_arr, 1u);
        if (t == nCTA - 1) {
            atomicExch(&g_bar_arr, 0u);
            __threadfence();
            atomicAdd(&g_bar_gen, 1u);
        } else {
            while (atomicAdd(&g_bar_gen, 0u) == gen) { __nanosleep(64); }
        }
        __threadfence();
    }
    __syncthreads();
}

// ---------------- 128x256-tile pipelined fp16 GEMM body ----------------------
// C[m,n] = alpha * sum_k A(m,k)*B(k,n); 128x256 tile; warps 2m x 4n = 64x64 each.
// AT=0: A [m][k]; AT=1: A [k][m]. BT=0: B [k][n]; BT=1: B [n][k]. fp32 out.
template <int AT, int BT>
__device__ __forceinline__ void gemm_body256(
    const __half* Ap, const __half* Bp, float* Cv,
    int lda, int ldb, int ldc, int Kc, float alpha,
    __half* As, __half* Bs)
{
    const int tid = threadIdx.x, wid = tid >> 5;
    const int warp_m = (wid & 1) * 64;
    const int warp_n = (wid >> 1) * 64;

    wmma::fragment<wmma::accumulator, 16, 16, 16, float> acc[4][4];
    #pragma unroll
    for (int i = 0; i < 4; i++)
        #pragma unroll
        for (int j = 0; j < 4; j++)
            wmma::fill_fragment(acc[i][j], 0.0f);

    using ALay = std::conditional_t<AT == 0, wmma::row_major, wmma::col_major>;
    using BLay = std::conditional_t<BT == 0, wmma::row_major, wmma::col_major>;

    auto stage = [&](int itile) {
        const int buf = itile % NST;
        const int kt = itile * 32;
        // A tile: 4096 halves = 512 chunks -> 2/thread
        #pragma unroll
        for (int q = 0; q < 2; q++) {
            int idx = tid + q * 256;
            if constexpr (AT == 0) {
                int r = idx >> 2, c = (idx & 3) * 8;
                cp16(As + buf * ASZ + r * PAD32 + c, Ap + (long)r * lda + kt + c);
            } else {
                int r = idx >> 4, c = (idx & 15) * 8;
                cp16(As + buf * ASZ + r * PADM + c, Ap + (long)(kt + r) * lda + c);
            }
        }
        // B tile: 8192 halves = 1024 chunks -> 4/thread
        #pragma unroll
        for (int q = 0; q < 4; q++) {
            int idx = tid + q * 256;
            if constexpr (BT == 0) {
                int r = idx >> 5, c = (idx & 31) * 8;
                cp16(Bs + buf * BSZ + r * PADN + c, Bp + (long)(kt + r) * ldb + c);
            } else {
                int r = idx >> 2, c = (idx & 3) * 8;
                cp16(Bs + buf * BSZ + r * PAD32 + c, Bp + (long)r * ldb + kt + c);
            }
        }
    };

    const int nIter = Kc >> 5;
    stage(0);
    CP_COMMIT();

    for (int it = 0; it < nIter; it++) {
        cp_wait<0>();            // tile it resident
        __syncthreads();
        if (it + 1 < nIter) { stage(it + 1); CP_COMMIT(); }

        const __half* Ab = As + (it % NST) * ASZ;
        const __half* Bb = Bs + (it % NST) * BSZ;
        #pragma unroll
        for (int ks = 0; ks < 32; ks += 16) {
            wmma::fragment<wmma::matrix_a, 16, 16, 16, __half, ALay> af[4];
            wmma::fragment<wmma::matrix_b, 16, 16, 16, __half, BLay> bf[4];
            #pragma unroll
            for (int i = 0; i < 4; i++) {
                if constexpr (AT == 0)
                    wmma::load_matrix_sync(af[i], Ab + (warp_m + i * 16) * PAD32 + ks, PAD32);
                else
                    wmma::load_matrix_sync(af[i], Ab + ks * PADM + warp_m + i * 16, PADM);
            }
            #pragma unroll
            for (int j = 0; j < 4; j++) {
                if constexpr (BT == 0)
                    wmma::load_matrix_sync(bf[j], Bb + ks * PADN + warp_n + j * 16, PADN);
                else
                    wmma::load_matrix_sync(bf[j], Bb + (warp_n + j * 16) * PAD32 + ks, PAD32);
            }
            #pragma unroll
            for (int i = 0; i < 4; i++)
                #pragma unroll
                for (int j = 0; j < 4; j++)
                    wmma::mma_sync(acc[i][j], af[i], bf[j], acc[i][j]);
        }
        __syncthreads();         // all warps done with buffer before restage
    }

    #pragma unroll
    for (int i = 0; i < 4; i++)
        #pragma unroll
        for (int j = 0; j < 4; j++) {
            #pragma unroll
            for (int t = 0; t < acc[i][j].num_elements; t++)
                acc[i][j].x[t] *= alpha;
            wmma::store_matrix_sync(Cv + (long)(warp_m + i * 16) * ldc + warp_n + j * 16,
                                    acc[i][j], ldc, wmma::mem_row_major);
        }
}

// ---------------- 128x256 kernel wrapper ----------------
// blockIdx.x = m-block; blockIdx.y = k-split; blockIdx.z = batch. n0 = 0 (full N).
template <int AT, int BT>
__global__ __launch_bounds__(256) void gemm256_k(
    const __half* __restrict__ A, const __half* __restrict__ B, float* C,
    int lda, int ldb, int ldc, int Kc,
    long sAz, long sBz, long sCz, long sCy, float alpha)
{
    extern __shared__ __half smem[];
    __half* As = smem;
    __half* Bs = smem + NST * ASZ;
    const int bx = blockIdx.x, by = blockIdx.y, bz = blockIdx.z;
    const int m0 = bx * 128;

    const __half* Ab;
    if constexpr (AT == 0) Ab = A + (long)bz * sAz + (long)m0 * lda + (long)by * Kc;
    else                   Ab = A + (long)bz * sAz + (long)by * Kc * lda + m0;
    const __half* Bb;
    if constexpr (BT == 0) Bb = B + (long)bz * sBz + (long)by * Kc * ldb;
    else                   Bb = B + (long)bz * sBz + (long)by * Kc;
    float* Cb = C + (long)bz * sCz + (long)by * sCy + (long)m0 * ldc;

    gemm_body256<AT, BT>(Ab, Bb, Cb, lda, ldb, ldc, Kc, alpha, As, Bs);
}

// ======================= mid-chain machinery (unchanged R13) =================
template <int OUTH>
__device__ __forceinline__ void gemm_epilogue(
    wmma::fragment<wmma::accumulator, 16, 16, 16, float> (&acc)[4][2],
    void* Cv, int ldc, float alpha, __half* As, int warp_m, int warp_n)
{
    const int tid = threadIdx.x, wid = tid >> 5;
    if constexpr (OUTH == 0) {
        float* Cb = (float*)Cv;
        #pragma unroll
        for (int i = 0; i < 4; i++)
            #pragma unroll
            for (int j = 0; j < 2; j++) {
                #pragma unroll
                for (int t = 0; t < acc[i][j].num_elements; t++)
                    acc[i][j].x[t] *= alpha;
                wmma::store_matrix_sync(Cb + (long)(warp_m + i * 16) * ldc + warp_n + j * 16,
                                        acc[i][j], ldc, wmma::mem_row_major);
            }
    } else {
        __half* Cb = (__half*)Cv;
        float* patch = ((float*)As) + wid * 256;
        const int lane = tid & 31;
        #pragma unroll
        for (int i = 0; i < 4; i++)
            #pragma unroll
            for (int j = 0; j < 2; j++) {
                wmma::store_matrix_sync(patch, acc[i][j], 16, wmma::mem_row_major);
                __syncwarp();
                #pragma unroll
                for (int e = 0; e < 8; e++) {
                    int el = lane + e * 32;
                    int rr = el >> 4, cc = el & 15;
                    Cb[(long)(warp_m + i * 16 + rr) * ldc + warp_n + j * 16 + cc] =
                        __float2half(patch[el] * alpha);
                }
                __syncwarp();
            }
    }
}

template <int AT, int BT, int OUTH, int NSTAGE>
__device__ __forceinline__ void gemm_body_pipe(
    const __half* Ap, const __half* Bp, void* Cv,
    int lda, int ldb, int ldc, int Kc, float alpha,
    __half* As, __half* Bs)
{
    const int tid = threadIdx.x, wid = tid >> 5;
    const int warp_m = (wid & 1) * 64;
    const int warp_n = (wid >> 1) * 32;

    wmma::fragment<wmma::accumulator, 16, 16, 16, float> acc[4][2];
    #pragma unroll
    for (int i = 0; i < 4; i++)
        #pragma unroll
        for (int j = 0; j < 2; j++)
            wmma::fill_fragment(acc[i][j], 0.0f);

    using ALay = std::conditional_t<AT == 0, wmma::row_major, wmma::col_major>;
    using BLay = std::conditional_t<BT == 0, wmma::row_major, wmma::col_major>;

    auto stage = [&](int itile) {
        const int buf = itile % NSTAGE;
        const int kt = itile * 32;
        #pragma unroll
        for (int q = 0; q < 2; q++) {
            int idx = tid + q * 256;
            if constexpr (AT == 0) {
                int r = idx >> 2, c = (idx & 3) * 8;
                cp16(As + buf * ABUF + r * PAD32 + c, Ap + (long)r * lda + kt + c);
            } else {
                int r = idx >> 4, c = (idx & 15) * 8;
                cp16(As + buf * ABUF + r * PADM + c, Ap + (long)(kt + r) * lda + c);
            }
        }
        #pragma unroll
        for (int q = 0; q < 2; q++) {
            int idx = tid + q * 256;
            if constexpr (BT == 0) {
                int r = idx >> 4, c = (idx & 15) * 8;
                cp16(Bs + buf * ABUF + r * PADM + c, Bp + (long)(kt + r) * ldb + c);
            } else {
                int r = idx >> 2, c = (idx & 3) * 8;
                cp16(Bs + buf * ABUF + r * PAD32 + c, Bp + (long)r * ldb + kt + c);
            }
        }
    };

    const int nIter = Kc >> 5;
    #pragma unroll
    for (int s = 0; s < NSTAGE - 1; s++)
        if (s < nIter) { stage(s); CP_COMMIT(); }

    for (int it = 0; it < nIter; it++) {
        if (it == nIter - 1) cp_wait<0>();
        else                 cp_wait<NSTAGE - 2>();
        __syncthreads();
        if (it + NSTAGE - 1 < nIter) { stage(it + NSTAGE - 1); CP_COMMIT(); }

        const __half* Ab = As + (it % NSTAGE) * ABUF;
        const __half* Bb = Bs + (it % NSTAGE) * ABUF;
        #pragma unroll
        for (int ks = 0; ks < 32; ks += 16) {
            wmma::fragment<wmma::matrix_a, 16, 16, 16, __half, ALay> af[4];
            wmma::fragment<wmma::matrix_b, 16, 16, 16, __half, BLay> bf[2];
            #pragma unroll
            for (int i = 0; i < 4; i++) {
                if constexpr (AT == 0)
                    wmma::load_matrix_sync(af[i], Ab + (warp_m + i * 16) * PAD32 + ks, PAD32);
                else
                    wmma::load_matrix_sync(af[i], Ab + ks * PADM + warp_m + i * 16, PADM);
            }
            #pragma unroll
            for (int j = 0; j < 2; j++) {
                if constexpr (BT == 0)
                    wmma::load_matrix_sync(bf[j], Bb + ks * PADM + warp_n + j * 16, PADM);
                else
                    wmma::load_matrix_sync(bf[j], Bb + (warp_n + j * 16) * PAD32 + ks, PAD32);
            }
            #pragma unroll
            for (int i = 0; i < 4; i++)
                #pragma unroll
                for (int j = 0; j < 2; j++)
                    wmma::mma_sync(acc[i][j], af[i], bf[j], acc[i][j]);
        }
    }
    if constexpr (OUTH == 1) __syncthreads();
    gemm_epilogue<OUTH>(acc, Cv, ldc, alpha, As, warp_m, warp_n);
}

template <int AT, int OUTH>
__device__ __forceinline__ void gemm_body_f32(
    const float* Ap, const float* Bp, void* Cv,
    int lda, int ldb, int ldc, int Kc, float alpha,
    __half* As, __half* Bs)
{
    const int tid = threadIdx.x, wid = tid >> 5;
    const int warp_m = (wid & 1) * 64;
    const int warp_n = (wid >> 1) * 32;

    wmma::fragment<wmma::accumulator, 16, 16, 16, float> acc[4][2];
    #pragma unroll
    for (int i = 0; i < 4; i++)
        #pragma unroll
        for (int j = 0; j < 2; j++)
            wmma::fill_fragment(acc[i][j], 0.0f);

    using ALay = std::conditional_t<AT == 0, wmma::row_major, wmma::col_major>;

    for (int kt = 0; kt < Kc; kt += 32) {
        if constexpr (AT == 0) {
            const float* Aq = Ap + kt;
            #pragma unroll
            for (int q = 0; q < 4; q++) {
                int idx = tid + q * 256;
                int r = idx >> 3, c = (idx & 7) * 4;
                float4 v = *(const float4*)(Aq + (long)r * lda + c);
                __half2 h0 = __floats2half2_rn(v.x, v.y);
                __half2 h1 = __floats2half2_rn(v.z, v.w);
                uint2 o; o.x = *(uint32_t*)&h0; o.y = *(uint32_t*)&h1;
                *(uint2*)(As + r * PAD32 + c) = o;
            }
        } else {
            const float* Aq = Ap + (long)kt * lda;
            #pragma unroll
            for (int q = 0; q < 4; q++) {
                int idx = tid + q * 256;
                int r = idx >> 5, c = (idx & 31) * 4;
                float4 v = *(const float4*)(Aq + (long)r * lda + c);
                __half2 h0 = __floats2half2_rn(v.x, v.y);
                __half2 h1 = __floats2half2_rn(v.z, v.w);
                uint2 o; o.x = *(uint32_t*)&h0; o.y = *(uint32_t*)&h1;
                *(uint2*)(As + r * PADM + c) = o;
            }
        }
        {
            const float* Bq = Bp + (long)kt * ldb;
            #pragma unroll
            for (int q = 0; q < 4; q++) {
                int idx = tid + q * 256;
                int r = idx >> 5, c = (idx & 31) * 4;
                float4 v = *(const float4*)(Bq + (long)r * ldb + c);
                __half2 h0 = __floats2half2_rn(v.x, v.y);
                __half2 h1 = __floats2half2_rn(v.z, v.w);
                uint2 o; o.x = *(uint32_t*)&h0; o.y = *(uint32_t*)&h1;
                *(uint2*)(Bs + r * PADM + c) = o;
            }
        }
        __syncthreads();
        #pragma unroll
        for (int ks = 0; ks < 32; ks += 16) {
            wmma::fragment<wmma::matrix_a, 16, 16, 16, __half, ALay> af[4];
            wmma::fragment<wmma::matrix_b, 16, 16, 16, __half, wmma::row_major> bf[2];
            #pragma unroll
            for (int i = 0; i < 4; i++) {
                if constexpr (AT == 0)
                    wmma::load_matrix_sync(af[i], As + (warp_m + i * 16) * PAD32 + ks, PAD32);
                else
                    wmma::load_matrix_sync(af[i], As + ks * PADM + warp_m + i * 16, PADM);
            }
            #pragma unroll
            for (int j = 0; j < 2; j++)
                wmma::load_matrix_sync(bf[j], Bs + ks * PADM + warp_n + j * 16, PADM);
            #pragma unroll
            for (int i = 0; i < 4; i++)
                #pragma unroll
                for (int j = 0; j < 2; j++)
                    wmma::mma_sync(acc[i][j], af[i], bf[j], acc[i][j]);
        }
        __syncthreads();
    }
    gemm_epilogue<OUTH>(acc, Cv, ldc, alpha, As, warp_m, warp_n);
}

__global__ __launch_bounds__(256, 2) void mid_chain(
    const float* __restrict__ Wo, const float* __restrict__ Wv,
    const float* __restrict__ Wk, const float* __restrict__ Wq,
    const float* __restrict__ part,
    __half* __restrict__ Gh, __half* __restrict__ R2, __half* __restrict__ P2,
    __half* __restrict__ U2, __half* __restrict__ T2)
{
    __shared__ __align__(32) __half As[2 * ABUF];
    __shared__ __align__(32) __half Bs[2 * ABUF];
    const int cta = blockIdx.x;
    const long EE = (long)E_ * E_;

    if (cta < 8) {
        const int bx = cta & 3;
        const int m0 = (bx >> 1) * 128, n0 = (bx & 1) * 128;
        if (cta < 4)
            gemm_body_f32<0, 1>(Wo + (long)m0 * E_, Wv + n0,
                                (void*)(R2 + (long)m0 * E_ + n0),
                                E_, E_, E_, E_, 1.0f, As, Bs);
        else
            gemm_body_f32<1, 1>(Wk + m0, Wq + n0,
                                (void*)(P2 + (long)m0 * E_ + n0),
                                E_, E_, E_, E_, 1.0f, As, Bs);
    } else {
        for (int i4 = (cta - 8) * 256 + threadIdx.x; i4 < B_ * E_ * E_ / 4;
             i4 += (NMID - 8) * 256) {
            const int b = i4 >> 14;
            const int r = i4 & 16383;
            const float4* p = (const float4*)part + (long)b * GSPLIT * 16384 + r;
            float4 s = make_float4(0.f, 0.f, 0.f, 0.f);
            #pragma unroll
            for (int q = 0; q < GSPLIT; q++) {
                float4 v = p[(long)q * 16384];
                s.x += v.x; s.y += v.y; s.z += v.z; s.w += v.w;
            }
            __half2 h0 = __floats2half2_rn(s.x, s.y);
            __half2 h1 = __floats2half2_rn(s.z, s.w);
            uint2 o;
            o.x = *(uint32_t*)&h0;
            o.y = *(uint32_t*)&h1;
            *((uint2*)Gh + i4) = o;
        }
    }
    grid_barrier(NMID);

    if (cta < 16) {
        const int bz = cta >> 2, bx = cta & 3;
        const int m0 = (bx >> 1) * 128, n0 = (bx & 1) * 128;
        gemm_body_pipe<0, 0, 1, 2>(R2 + (long)m0 * E_, Gh + (long)bz * EE + n0,
                                   (void*)(U2 + (long)bz * EE + (long)m0 * E_ + n0),
                                   E_, E_, E_, E_, 1.0f, As, Bs);
    }
    grid_barrier(NMID);

    if (cta < 16) {
        const int bz = cta >> 2, bx = cta & 3;
        const int m0 = (bx >> 1) * 128, n0 = (bx & 1) * 128;
        gemm_body_pipe<0, 0, 1, 2>(U2 + (long)bz * EE + (long)m0 * E_, P2 + n0,
                                   (void*)(T2 + (long)bz * EE + (long)m0 * E_ + n0),
                                   E_, E_, E_, E_, 1.0f, As, Bs);
    }
}

// ---------------- flat convert x -> fp16 ----------
__global__ __launch_bounds__(256) void convert_x(
    const float4* __restrict__ x4, uint2* __restrict__ xh4)
{
    const int i = blockIdx.x * 256 + threadIdx.x;
    float4 v = x4[i];
    __half2 h0 = __floats2half2_rn(v.x, v.y);
    __half2 h1 = __floats2half2_rn(v.z, v.w);
    uint2 o;
    o.x = *(uint32_t*)&h0;
    o.y = *(uint32_t*)&h1;
    xh4[i] = o;
}

// ---------------- launch ----------------
extern "C" void kernel_launch(void* const* d_in, const int* in_sizes, int n_in,
                              void* d_out, int out_size)
{
    const float* x  = (const float*)d_in[0];
    const float* Wq = (const float*)d_in[1];
    const float* Wk = (const float*)d_in[2];
    const float* Wv = (const float*)d_in[3];
    const float* Wo = (const float*)d_in[4];
    float* out = (float*)d_out;

    __half *pxh, *pGh, *pR2h, *pP2h, *pU2h, *pT2h;
    float *pPart;
    cudaGetSymbolAddress((void**)&pxh, g_xh);
    cudaGetSymbolAddress((void**)&pPart, g_part);
    cudaGetSymbolAddress((void**)&pGh, g_Gh);
    cudaGetSymbolAddress((void**)&pR2h, g_R2h);
    cudaGetSymbolAddress((void**)&pP2h, g_P2h);
    cudaGetSymbolAddress((void**)&pU2h, g_U2h);
    cudaGetSymbolAddress((void**)&pT2h, g_T2h);

    const long EE = (long)E_ * E_;
    const long SE = (long)S_ * E_;
    const int SMEM256 = NST * (ASZ + BSZ) * 2;   // 61440 B (proven config)

    cudaFuncSetAttribute(gemm256_k<1, 0>,
                         cudaFuncAttributeMaxDynamicSharedMemorySize, SMEM256);
    cudaFuncSetAttribute(gemm256_k<0, 1>,
                         cudaFuncAttributeMaxDynamicSharedMemorySize, SMEM256);

    // 1) flat convert x -> fp16 row-major
    convert_x<<<B_ * S_ * E_ / 4 / 256, 256>>>((const float4*)x, (uint2*)pxh);

    // 2) Gram partials: A = x as [k=s][m=e] (AT=1), B = x as [k=s][n=f] (BT=0)
    //    grid 2 x 16 x 4 = 128 CTAs, Kc = 256
    gemm256_k<1, 0><<<dim3(2, GSPLIT, B_), 256, SMEM256>>>(
        pxh, pxh, pPart, E_, E_, E_, S_ / GSPLIT,
        SE, SE, (long)GSPLIT * EE, EE, 1.0f);

    // 3) persistent middle: reduce + R2/P2 (concurrent) -> U2 -> T2
    mid_chain<<<NMID, 256>>>(Wo, Wv, Wk, Wq, pPart, pGh, pR2h, pP2h, pU2h, pT2h);

    // 4) final: out[s,g] = 1e-11 * sum_f x[s,f] * T2[g,f]  (AT=0, BT=1)
    //    grid 32 x 1 x 4 = 128 CTAs
    gemm256_k<0, 1><<<dim3(32, 1, B_), 256, SMEM256>>>(
        pxh, pT2h, out, E_, E_, E_, E_,
        SE, EE, SE, 0, 1e-11f);
}